// round 2
// baseline (speedup 1.0000x reference)
#include <cuda_runtime.h>
#include <math.h>

// ---------------------------------------------------------------------------
// Problem constants
// ---------------------------------------------------------------------------
#define BATCH 8
#define SEQ   256
#define NTOK  2048          // BATCH*SEQ
#define DD    1152
#define DD3   3456          // 3*D
#define DD4   4608          // 4*D
#define MH    4608          // MLP hidden
#define NE    8
#define NH    16
#define HD    72
#define LN_EPS 1e-6f

// ---------------------------------------------------------------------------
// Device scratch (no allocations allowed)
// ---------------------------------------------------------------------------
__device__ float g_mod[BATCH * DD4];          // shift|scale|gate_msa|gate_mlp
__device__ float g_h[NTOK * DD];              // modulated LN1 output
__device__ float g_qkv[NTOK * DD3];
__device__ float g_ao[NTOK * DD];             // attention output
__device__ float g_nx[NTOK * DD];             // LN2 output
__device__ float g_score[NTOK * 2];
__device__ int   g_topidx[NTOK * 2];
__device__ int   g_slot_of[NTOK * 2];
__device__ int   g_bucket_tok[NTOK * 2];
__device__ int   g_off[NE];
__device__ int   g_cnt[NE];
__device__ float g_h1[NTOK * 2 * MH];         // 75.5 MB
__device__ float g_eo[NTOK * 2 * DD];         // 18.9 MB

// ---------------------------------------------------------------------------
// Helpers
// ---------------------------------------------------------------------------
__device__ __forceinline__ float gelu_tanh(float x) {
    float x3 = x * x * x;
    return 0.5f * x * (1.f + tanhf(0.7978845608028654f * (x + 0.044715f * x3)));
}

// ---------------------------------------------------------------------------
// Kernel 1: mod = silu(c) @ adaln_w + adaln_b        (8 x 4608)
// grid (36, 8), block 128
// ---------------------------------------------------------------------------
__global__ void adaln_kernel(const float* __restrict__ c,
                             const float* __restrict__ w,
                             const float* __restrict__ b) {
    int bb  = blockIdx.y;
    int col = blockIdx.x * 128 + threadIdx.x;
    __shared__ float cs[DD];
    for (int i = threadIdx.x; i < DD; i += 128) {
        float v = c[bb * DD + i];
        cs[i] = v / (1.f + __expf(-v));
    }
    __syncthreads();
    float acc = b[col];
    #pragma unroll 4
    for (int i = 0; i < DD; i++)
        acc += cs[i] * w[(size_t)i * DD4 + col];
    g_mod[bb * DD4 + col] = acc;
}

// ---------------------------------------------------------------------------
// Kernel 2/6: LayerNorm.  MODE 0: h = ln(x)*(1+scale)+shift -> g_h
//                         MODE 1: nx = ln(in) -> g_nx
// grid NTOK, block 256
// ---------------------------------------------------------------------------
template <int MODE>
__global__ void ln_kernel(const float* __restrict__ in) {
    int t = blockIdx.x;
    const float* xr = in + (size_t)t * DD;
    int tid = threadIdx.x, lane = tid & 31, warp = tid >> 5;

    float s = 0.f, s2 = 0.f;
    for (int i = tid; i < DD; i += 256) {
        float v = xr[i];
        s += v; s2 += v * v;
    }
    #pragma unroll
    for (int o = 16; o; o >>= 1) {
        s  += __shfl_xor_sync(0xffffffffu, s,  o);
        s2 += __shfl_xor_sync(0xffffffffu, s2, o);
    }
    __shared__ float ws[8], ws2[8];
    __shared__ float mean_s, rstd_s;
    if (lane == 0) { ws[warp] = s; ws2[warp] = s2; }
    __syncthreads();
    if (warp == 0) {
        s  = (lane < 8) ? ws[lane]  : 0.f;
        s2 = (lane < 8) ? ws2[lane] : 0.f;
        #pragma unroll
        for (int o = 4; o; o >>= 1) {
            s  += __shfl_xor_sync(0xffffffffu, s,  o);
            s2 += __shfl_xor_sync(0xffffffffu, s2, o);
        }
        if (lane == 0) {
            float m = s * (1.f / DD);
            float v = s2 * (1.f / DD) - m * m;
            mean_s = m;
            rstd_s = rsqrtf(v + LN_EPS);
        }
    }
    __syncthreads();
    float m = mean_s, rstd = rstd_s;
    int bb = t >> 8;
    for (int i = tid; i < DD; i += 256) {
        float v = (xr[i] - m) * rstd;
        if (MODE == 0) {
            float sc = g_mod[bb * DD4 + DD + i];   // scale_msa
            float sh = g_mod[bb * DD4 + i];        // shift_msa
            v = v * (1.f + sc) + sh;
            g_h[(size_t)t * DD + i] = v;
        } else {
            g_nx[(size_t)t * DD + i] = v;
        }
    }
}

// ---------------------------------------------------------------------------
// Generic tiled SGEMM, 64x64x16, 256 threads, 4x4 per thread.
// MODE 0: g_qkv = g_h @ W + bias
// MODE 1: Cout(d_out) = xres + gate_msa * (g_ao @ W + bias)
// MODE 2: per-expert: g_h1 = gelu(gather(g_nx) @ w1[e] + b1[e])
// MODE 3: per-expert: g_eo = g_h1 @ w2[e] + b2[e]
// ---------------------------------------------------------------------------
template <int MODE>
__global__ __launch_bounds__(256)
void gemm_k(const float* __restrict__ W0, const float* __restrict__ bias0,
            const float* __restrict__ xres, float* __restrict__ Cout,
            int M, int Nn, int Kk) {
    int e = blockIdx.z;
    const float* A;
    const float* W = W0;
    const float* bias = bias0;
    float* C;
    const int* gather = nullptr;
    int rowbase = 0;

    if (MODE == 0) { A = g_h;  C = g_qkv; }
    else if (MODE == 1) { A = g_ao; C = Cout; }
    else if (MODE == 2) {
        M = g_cnt[e]; rowbase = g_off[e];
        gather = g_bucket_tok + rowbase;
        A = g_nx;
        W = W0 + (size_t)e * DD * MH;
        bias = bias0 + e * MH;
        C = g_h1;
    } else {
        M = g_cnt[e]; rowbase = g_off[e];
        A = g_h1 + (size_t)rowbase * MH;
        W = W0 + (size_t)e * MH * DD;
        bias = bias0 + e * DD;
        C = g_eo;
    }

    int row0 = blockIdx.y * 64;
    if (row0 >= M) return;
    int col0 = blockIdx.x * 64;

    __shared__ float As[64][17];
    __shared__ __align__(16) float Bs[16][64];

    int tid = threadIdx.x;
    int tx = tid & 15, ty = tid >> 4;

    const float* arow[4];
    #pragma unroll
    for (int l = 0; l < 4; l++) {
        int idx = tid + l * 256;
        int r = idx >> 4;
        if (row0 + r < M) {
            if (MODE == 2) arow[l] = A + (size_t)gather[row0 + r] * Kk;
            else           arow[l] = A + (size_t)(row0 + r) * Kk;
        } else arow[l] = nullptr;
    }

    float acc[4][4];
    #pragma unroll
    for (int i = 0; i < 4; i++)
        #pragma unroll
        for (int j = 0; j < 4; j++) acc[i][j] = 0.f;

    for (int k0 = 0; k0 < Kk; k0 += 16) {
        #pragma unroll
        for (int l = 0; l < 4; l++) {
            int idx = tid + l * 256;
            int r = idx >> 4, cc = idx & 15;
            As[r][cc] = arow[l] ? arow[l][k0 + cc] : 0.f;
        }
        #pragma unroll
        for (int l = 0; l < 4; l++) {
            int idx = tid + l * 256;
            int r = idx >> 6, cc = idx & 63;
            Bs[r][cc] = W[(size_t)(k0 + r) * Nn + col0 + cc];
        }
        __syncthreads();
        #pragma unroll
        for (int k = 0; k < 16; k++) {
            float a0 = As[ty * 4 + 0][k];
            float a1 = As[ty * 4 + 1][k];
            float a2 = As[ty * 4 + 2][k];
            float a3 = As[ty * 4 + 3][k];
            float4 b = *(const float4*)&Bs[k][tx * 4];
            acc[0][0] += a0 * b.x; acc[0][1] += a0 * b.y; acc[0][2] += a0 * b.z; acc[0][3] += a0 * b.w;
            acc[1][0] += a1 * b.x; acc[1][1] += a1 * b.y; acc[1][2] += a1 * b.z; acc[1][3] += a1 * b.w;
            acc[2][0] += a2 * b.x; acc[2][1] += a2 * b.y; acc[2][2] += a2 * b.z; acc[2][3] += a2 * b.w;
            acc[3][0] += a3 * b.x; acc[3][1] += a3 * b.y; acc[3][2] += a3 * b.z; acc[3][3] += a3 * b.w;
        }
        __syncthreads();
    }

    #pragma unroll
    for (int i = 0; i < 4; i++) {
        int grow = row0 + ty * 4 + i;
        if (grow >= M) continue;
        size_t crow = (size_t)(rowbase + grow) * Nn;
        #pragma unroll
        for (int j = 0; j < 4; j++) {
            int cc = col0 + tx * 4 + j;
            float v = acc[i][j] + bias[cc];
            if (MODE == 1) {
                int bb = grow >> 8;
                v = xres[(size_t)grow * DD + cc] + g_mod[bb * DD4 + 2 * DD + cc] * v;
            } else if (MODE == 2) {
                v = gelu_tanh(v);
            }
            C[crow + cc] = v;
        }
    }
}

// ---------------------------------------------------------------------------
// Kernel 4: attention, one block per (head, batch). K,V staged in smem
// (row stride 73 -> conflict-free), each warp owns 32 queries.
// grid (NH, BATCH), block 256, dyn smem 157696 B
// ---------------------------------------------------------------------------
__global__ void attn_kernel() {
    int h = blockIdx.x, b = blockIdx.y;
    extern __shared__ float sm[];
    float* Ks = sm;                 // 256*73
    float* Vs = sm + 256 * 73;      // 256*73
    float* Ps = sm + 2 * 256 * 73;  // 8*256

    const float* base = g_qkv + (size_t)b * SEQ * DD3;
    int tid = threadIdx.x;

    for (int i = tid; i < SEQ * HD; i += 256) {
        int r = i / HD, d = i - r * HD;
        size_t g = (size_t)r * DD3 + h * HD + d;
        Ks[r * 73 + d] = base[g + DD];
        Vs[r * 73 + d] = base[g + 2 * DD];
    }
    __syncthreads();

    int warp = tid >> 5, lane = tid & 31;
    float* ps = Ps + warp * 256;
    const float scale = 0.11785113019775793f;  // 1/sqrt(72)

    for (int q = warp; q < SEQ; q += 8) {
        const float* qv = base + (size_t)q * DD3 + h * HD;  // broadcast reads (L1)
        float sloc[8];
        float mx = -1e30f;
        #pragma unroll
        for (int kk = 0; kk < 8; kk++) {
            const float* kv = Ks + (lane + kk * 32) * 73;
            float s = 0.f;
            #pragma unroll
            for (int d = 0; d < HD; d++) s += qv[d] * kv[d];
            s *= scale;
            sloc[kk] = s;
            mx = fmaxf(mx, s);
        }
        #pragma unroll
        for (int o = 16; o; o >>= 1) mx = fmaxf(mx, __shfl_xor_sync(0xffffffffu, mx, o));
        float sum = 0.f;
        #pragma unroll
        for (int kk = 0; kk < 8; kk++) { sloc[kk] = __expf(sloc[kk] - mx); sum += sloc[kk]; }
        #pragma unroll
        for (int o = 16; o; o >>= 1) sum += __shfl_xor_sync(0xffffffffu, sum, o);
        float inv = 1.f / sum;
        #pragma unroll
        for (int kk = 0; kk < 8; kk++) ps[lane + kk * 32] = sloc[kk] * inv;
        __syncwarp();

        float o0 = 0.f, o1 = 0.f, o2 = 0.f;
        for (int k = 0; k < SEQ; k++) {
            float p = ps[k];
            const float* vr = Vs + k * 73;
            o0 += p * vr[lane];
            o1 += p * vr[lane + 32];
            if (lane < 8) o2 += p * vr[lane + 64];
        }
        float* orow = g_ao + (size_t)(b * SEQ + q) * DD + h * HD;
        orow[lane] = o0;
        orow[lane + 32] = o1;
        if (lane < 8) orow[lane + 64] = o2;
    }
}

// ---------------------------------------------------------------------------
// Kernel 7: router. One warp per token: 8 logits, top-2, softmax(2).
// grid 256, block 256
// ---------------------------------------------------------------------------
__global__ void router_kernel(const float* __restrict__ gw,
                              const float* __restrict__ gb) {
    int t = blockIdx.x * 8 + (threadIdx.x >> 5);
    int lane = threadIdx.x & 31;
    const float* xr = g_nx + (size_t)t * DD;
    float acc[NE];
    #pragma unroll
    for (int e = 0; e < NE; e++) acc[e] = 0.f;
    for (int i = lane; i < DD; i += 32) {
        float v = xr[i];
        const float* g = gw + i * NE;
        #pragma unroll
        for (int e = 0; e < NE; e++) acc[e] += v * g[e];
    }
    #pragma unroll
    for (int e = 0; e < NE; e++)
        #pragma unroll
        for (int o = 16; o; o >>= 1) acc[e] += __shfl_xor_sync(0xffffffffu, acc[e], o);
    if (lane == 0) {
        float best = -1e30f, second = -1e30f; int bi = 0, si = 0;
        #pragma unroll
        for (int e = 0; e < NE; e++) {
            float v = acc[e] + gb[e];
            if (v > best) { second = best; si = bi; best = v; bi = e; }
            else if (v > second) { second = v; si = e; }
        }
        float e1 = __expf(second - best);
        float inv = 1.f / (1.f + e1);
        g_topidx[t * 2] = bi;  g_topidx[t * 2 + 1] = si;
        g_score[t * 2] = inv;  g_score[t * 2 + 1] = e1 * inv;
    }
}

// ---------------------------------------------------------------------------
// Kernel 8: bucketize tokens per expert. Single block.
// ---------------------------------------------------------------------------
__global__ void bucketize_kernel() {
    __shared__ int cnt[NE], off[NE], cur[NE];
    int tid = threadIdx.x;
    if (tid < NE) cnt[tid] = 0;
    __syncthreads();
    for (int t = tid; t < NTOK; t += 256) {
        atomicAdd(&cnt[g_topidx[t * 2]], 1);
        atomicAdd(&cnt[g_topidx[t * 2 + 1]], 1);
    }
    __syncthreads();
    if (tid == 0) {
        int o = 0;
        for (int e = 0; e < NE; e++) {
            off[e] = o; g_off[e] = o; g_cnt[e] = cnt[e];
            o += cnt[e];
        }
    }
    __syncthreads();
    if (tid < NE) cur[tid] = off[tid];
    __syncthreads();
    for (int t = tid; t < NTOK; t += 256) {
        #pragma unroll
        for (int k = 0; k < 2; k++) {
            int e = g_topidx[t * 2 + k];
            int p = atomicAdd(&cur[e], 1);
            g_bucket_tok[p] = t;
            g_slot_of[t * 2 + k] = p;
        }
    }
}

// ---------------------------------------------------------------------------
// Kernel 11: out += gate_mlp * (s0*eo[slot0] + s1*eo[slot1])
// grid NTOK, block 256
// ---------------------------------------------------------------------------
__global__ void final_kernel(float* __restrict__ out) {
    int t = blockIdx.x;
    int bb = t >> 8;
    int sl0 = g_slot_of[t * 2], sl1 = g_slot_of[t * 2 + 1];
    float s0 = g_score[t * 2], s1 = g_score[t * 2 + 1];
    const float* gm = g_mod + bb * DD4 + 3 * DD;
    const float* e0 = g_eo + (size_t)sl0 * DD;
    const float* e1 = g_eo + (size_t)sl1 * DD;
    float* o = out + (size_t)t * DD;
    for (int i = threadIdx.x; i < DD; i += 256)
        o[i] += gm[i] * (s0 * e0[i] + s1 * e1[i]);
}

// ---------------------------------------------------------------------------
// Launcher
// ---------------------------------------------------------------------------
extern "C" void kernel_launch(void* const* d_in, const int* in_sizes, int n_in,
                              void* d_out, int out_size) {
    (void)in_sizes; (void)n_in; (void)out_size;
    const float* x       = (const float*)d_in[0];
    const float* c       = (const float*)d_in[1];
    const float* qkv_w   = (const float*)d_in[2];
    const float* qkv_b   = (const float*)d_in[3];
    const float* proj_w  = (const float*)d_in[4];
    const float* proj_b  = (const float*)d_in[5];
    const float* adaln_w = (const float*)d_in[6];
    const float* adaln_b = (const float*)d_in[7];
    const float* gate_w  = (const float*)d_in[8];
    const float* gate_b  = (const float*)d_in[9];
    const float* w1      = (const float*)d_in[10];
    const float* b1      = (const float*)d_in[11];
    const float* w2      = (const float*)d_in[12];
    const float* b2      = (const float*)d_in[13];
    float* out = (float*)d_out;

    const int ATTN_SMEM = (2 * 256 * 73 + 8 * 256) * 4;  // 157696 B
    cudaFuncSetAttribute(attn_kernel, cudaFuncAttributeMaxDynamicSharedMemorySize,
                         ATTN_SMEM);

    // 1. adaLN modulation
    adaln_kernel<<<dim3(DD4 / 128, BATCH), 128>>>(c, adaln_w, adaln_b);
    // 2. LN1 + modulation
    ln_kernel<0><<<NTOK, 256>>>(x);
    // 3. qkv GEMM
    gemm_k<0><<<dim3(DD3 / 64, NTOK / 64, 1), 256>>>(qkv_w, qkv_b, nullptr, nullptr,
                                                     NTOK, DD3, DD);
    // 4. attention
    attn_kernel<<<dim3(NH, BATCH), 256, ATTN_SMEM>>>();
    // 5. proj GEMM + residual + gate_msa -> d_out (holds x after attention)
    gemm_k<1><<<dim3(DD / 64, NTOK / 64, 1), 256>>>(proj_w, proj_b, x, out,
                                                    NTOK, DD, DD);
    // 6. LN2
    ln_kernel<1><<<NTOK, 256>>>(out);
    // 7. router
    router_kernel<<<NTOK / 8, 256>>>(gate_w, gate_b);
    // 8. bucketize
    bucketize_kernel<<<1, 256>>>();
    // 9. MoE GEMM1 (gathered, gelu). grid covers worst-case M per expert.
    gemm_k<2><<<dim3(MH / 64, NTOK / 64, NE), 256>>>(w1, b1, nullptr, nullptr,
                                                     0, MH, DD);
    // 10. MoE GEMM2
    gemm_k<3><<<dim3(DD / 64, NTOK / 64, NE), 256>>>(w2, b2, nullptr, nullptr,
                                                     0, DD, MH);
    // 11. combine
    final_kernel<<<NTOK, 256>>>(out);
}

// round 5
// speedup vs baseline: 1.0665x; 1.0665x over previous
#include <cuda_runtime.h>
#include <math.h>
#include <stdint.h>

// ---------------------------------------------------------------------------
#define BATCH 8
#define SEQ   256
#define NTOK  2048
#define DD    1152
#define DD3   3456
#define DD4   4608
#define MH    4608
#define NE    8
#define NH    16
#define HD    72
#define LN_EPS 1e-6f

// ---------------------------------------------------------------------------
// Device scratch (no allocations allowed)
// ---------------------------------------------------------------------------
__device__ __align__(16) float g_mod[BATCH * DD4];
__device__ __align__(16) float g_h[NTOK * DD];
__device__ __align__(16) float g_qkv[NTOK * DD3];
__device__ __align__(16) float g_ao[NTOK * DD];
__device__ __align__(16) float g_nx[NTOK * DD];
__device__ float g_score[NTOK * 2];
__device__ int   g_topidx[NTOK * 2];
__device__ int   g_slot_of[NTOK * 2];
__device__ int   g_bucket_tok[NTOK * 2];
__device__ int   g_off[NE];
__device__ int   g_cnt[NE];
__device__ __align__(16) float g_h1[(size_t)NTOK * 2 * MH];
__device__ __align__(16) float g_eo[(size_t)NTOK * 2 * DD];

// ---------------------------------------------------------------------------
// Helpers
// ---------------------------------------------------------------------------
__device__ __forceinline__ float tf32r(float x) {
    float r; asm("cvt.rna.tf32.f32 %0, %1;" : "=f"(r) : "f"(x)); return r;
}
__device__ __forceinline__ void mma_tf32(float* d, const unsigned* a, const unsigned* b) {
    asm volatile(
        "mma.sync.aligned.m16n8k8.row.col.f32.tf32.tf32.f32 "
        "{%0,%1,%2,%3}, {%4,%5,%6,%7}, {%8,%9}, {%0,%1,%2,%3};"
        : "+f"(d[0]), "+f"(d[1]), "+f"(d[2]), "+f"(d[3])
        : "r"(a[0]), "r"(a[1]), "r"(a[2]), "r"(a[3]), "r"(b[0]), "r"(b[1]));
}
__device__ __forceinline__ float gelu_tanh(float x) {
    float x3 = x * x * x;
    return 0.5f * x * (1.f + tanhf(0.7978845608028654f * (x + 0.044715f * x3)));
}
// split x into hi (tf32) + lo (tf32 of residual)
__device__ __forceinline__ void split4(float4 v, float4& hi, float4& lo) {
    hi.x = tf32r(v.x); lo.x = tf32r(v.x - hi.x);
    hi.y = tf32r(v.y); lo.y = tf32r(v.y - hi.y);
    hi.z = tf32r(v.z); lo.z = tf32r(v.z - hi.z);
    hi.w = tf32r(v.w); lo.w = tf32r(v.w - hi.w);
}

// ---------------------------------------------------------------------------
// adaLN modulation: mod = silu(c) @ adaln_w + adaln_b
// ---------------------------------------------------------------------------
__global__ void adaln_kernel(const float* __restrict__ c,
                             const float* __restrict__ w,
                             const float* __restrict__ b) {
    int bb = blockIdx.y;
    int col = blockIdx.x * 128 + threadIdx.x;
    __shared__ float cs[DD];
    for (int i = threadIdx.x; i < DD; i += 128) {
        float v = c[bb * DD + i];
        cs[i] = v / (1.f + __expf(-v));
    }
    __syncthreads();
    float acc = b[col];
    #pragma unroll 4
    for (int i = 0; i < DD; i++)
        acc += cs[i] * w[(size_t)i * DD4 + col];
    g_mod[bb * DD4 + col] = acc;
}

// ---------------------------------------------------------------------------
// LayerNorm. MODE 0: h = ln(x)*(1+scale)+shift -> g_h ; MODE 1: -> g_nx
// ---------------------------------------------------------------------------
template <int MODE>
__global__ void ln_kernel(const float* __restrict__ in) {
    int t = blockIdx.x;
    const float* xr = in + (size_t)t * DD;
    int tid = threadIdx.x, lane = tid & 31, warp = tid >> 5;
    float s = 0.f, s2 = 0.f;
    for (int i = tid; i < DD; i += 256) { float v = xr[i]; s += v; s2 += v * v; }
    #pragma unroll
    for (int o = 16; o; o >>= 1) {
        s  += __shfl_xor_sync(0xffffffffu, s,  o);
        s2 += __shfl_xor_sync(0xffffffffu, s2, o);
    }
    __shared__ float ws[8], ws2[8], mean_s, rstd_s;
    if (lane == 0) { ws[warp] = s; ws2[warp] = s2; }
    __syncthreads();
    if (warp == 0) {
        s  = (lane < 8) ? ws[lane]  : 0.f;
        s2 = (lane < 8) ? ws2[lane] : 0.f;
        #pragma unroll
        for (int o = 4; o; o >>= 1) {
            s  += __shfl_xor_sync(0xffffffffu, s,  o);
            s2 += __shfl_xor_sync(0xffffffffu, s2, o);
        }
        if (lane == 0) {
            float m = s * (1.f / DD);
            float v = s2 * (1.f / DD) - m * m;
            mean_s = m; rstd_s = rsqrtf(v + LN_EPS);
        }
    }
    __syncthreads();
    float m = mean_s, rstd = rstd_s;
    int bb = t >> 8;
    for (int i = tid; i < DD; i += 256) {
        float v = (xr[i] - m) * rstd;
        if (MODE == 0) {
            float sc = g_mod[bb * DD4 + DD + i];
            float sh = g_mod[bb * DD4 + i];
            g_h[(size_t)t * DD + i] = v * (1.f + sc) + sh;
        } else {
            g_nx[(size_t)t * DD + i] = v;
        }
    }
}

// ---------------------------------------------------------------------------
// 3xTF32 tensor-core GEMM via mma.sync (compiles for compute_103).
// acc = Ahi*Bhi + Alo*Bhi + Ahi*Blo   (fp32 accumulate; ~1e-6 rel err)
// CTA tile 128x128, 8 warps (2x4), warp tile 64x32, K-chunk 32,
// double-buffered smem + register prefetch.
//   MODE 0: g_qkv = g_h @ qkv_w + b
//   MODE 1: d_out = xres + gate_msa * (g_ao @ proj_w + b)
//   MODE 2: g_h1 = gelu(gather(g_nx) @ w1[e] + b1[e])
//   MODE 3: g_eo = g_h1 @ w2[e] + b2[e]
// W is the ORIGINAL [K][N] row-major weight (row.col mma reads B[k][n]).
// ---------------------------------------------------------------------------
#define A_STRIDE 36          // 32 + 4 pad (floats)
#define B_STRIDE 136         // 128 + 8 pad (floats)
#define A_FLOATS (128 * A_STRIDE)                    // 4608
#define B_FLOATS (32 * B_STRIDE)                     // 4352
#define BUF_FLOATS (2 * A_FLOATS + 2 * B_FLOATS)     // 17920 (hi+lo)
#define GEMM_SMEM (2 * BUF_FLOATS * 4)               // 143360 B

template <int MODE>
__global__ __launch_bounds__(256, 1)
void gemm_tc(const float* __restrict__ W, const float* __restrict__ bias,
             const float* __restrict__ xres, float* __restrict__ Cout,
             int M, int Nn, int Kk) {
    int e = blockIdx.z;
    const float* A;
    float* C;
    const int* gather = nullptr;
    int rowbase = 0;

    if (MODE == 0)      { A = g_h;  C = g_qkv; }
    else if (MODE == 1) { A = g_ao; C = Cout; }
    else if (MODE == 2) {
        M = g_cnt[e]; rowbase = g_off[e];
        gather = g_bucket_tok + rowbase;
        A = g_nx;
        W = W + (size_t)e * DD * MH;
        bias = bias + e * MH;
        C = g_h1;
    } else {
        M = g_cnt[e]; rowbase = g_off[e];
        A = g_h1 + (size_t)rowbase * MH;
        W = W + (size_t)e * MH * DD;
        bias = bias + e * DD;
        C = g_eo;
    }

    int row0 = blockIdx.y * 128;
    if (row0 >= M) return;
    int col0 = blockIdx.x * 128;

    extern __shared__ __align__(16) float sm[];
    // per buffer: [Ahi | Alo | Bhi | Blo]
    float* sAh[2] = { sm,                          sm + BUF_FLOATS };
    float* sAl[2] = { sm + A_FLOATS,               sm + BUF_FLOATS + A_FLOATS };
    float* sBh[2] = { sm + 2 * A_FLOATS,           sm + BUF_FLOATS + 2 * A_FLOATS };
    float* sBl[2] = { sm + 2 * A_FLOATS + B_FLOATS, sm + BUF_FLOATS + 2 * A_FLOATS + B_FLOATS };

    int tid = threadIdx.x;
    int lane = tid & 31, wid = tid >> 5;
    int gid = lane >> 2, tig = lane & 3;
    int wm = wid >> 2, wn = wid & 3;       // warp tile: rows wm*64, cols wn*32

    // ---- staging maps -----------------------------------------------------
    int fA = tid & 7;
    const float* arow[4];
    unsigned aoff[4];
    #pragma unroll
    for (int j = 0; j < 4; j++) {
        int r = (tid >> 3) + 32 * j;
        int gr = row0 + r;
        if (gr > M - 1) gr = M - 1;
        if (MODE == 2) arow[j] = A + (size_t)gather[gr] * Kk + fA * 4;
        else           arow[j] = A + (size_t)gr * Kk + fA * 4;
        aoff[j] = (unsigned)(r * A_STRIDE + fA * 4);
    }
    int fB = tid & 31;
    const float* brow[4];
    unsigned boff[4];
    #pragma unroll
    for (int j = 0; j < 4; j++) {
        int r = (tid >> 5) + 8 * j;
        brow[j] = W + (size_t)r * Nn + col0 + fB * 4;
        boff[j] = (unsigned)(r * B_STRIDE + fB * 4);
    }
    size_t bstep = (size_t)32 * Nn;

    float acc[4][4][4];
    #pragma unroll
    for (int mi = 0; mi < 4; mi++)
        #pragma unroll
        for (int ni = 0; ni < 4; ni++)
            #pragma unroll
            for (int r = 0; r < 4; r++) acc[mi][ni][r] = 0.f;

    // ---- prologue: stage chunk 0 into buffer 0 -----------------------------
    #pragma unroll
    for (int j = 0; j < 4; j++) {
        float4 hi, lo;
        split4(*(const float4*)(arow[j]), hi, lo);
        *(float4*)(sAh[0] + aoff[j]) = hi;
        *(float4*)(sAl[0] + aoff[j]) = lo;
        split4(*(const float4*)(brow[j]), hi, lo);
        *(float4*)(sBh[0] + boff[j]) = hi;
        *(float4*)(sBl[0] + boff[j]) = lo;
    }
    __syncthreads();

    int nch = Kk / 32;
    for (int c = 0; c < nch; c++) {
        int cur = c & 1;
        float4 pa[4], pb[4];
        bool more = (c + 1 < nch);
        if (more) {
            int k0n = (c + 1) * 32;
            size_t bo = (size_t)(c + 1) * bstep;
            #pragma unroll
            for (int j = 0; j < 4; j++) {
                pa[j] = *(const float4*)(arow[j] + k0n);
                pb[j] = *(const float4*)(brow[j] + bo);
            }
        }

        const float* Ah = sAh[cur];
        const float* Al = sAl[cur];
        const float* Bh = sBh[cur];
        const float* Bl = sBl[cur];
        #pragma unroll
        for (int ks = 0; ks < 4; ks++) {
            int k = ks * 8;
            unsigned afh[4][4], afl[4][4];
            unsigned bfh[4][2], bfl[4][2];
            #pragma unroll
            for (int mi = 0; mi < 4; mi++) {
                int m = wm * 64 + mi * 16 + gid;
                int i0 = (m)     * A_STRIDE + k + tig;
                int i1 = (m + 8) * A_STRIDE + k + tig;
                afh[mi][0] = __float_as_uint(Ah[i0]);
                afh[mi][1] = __float_as_uint(Ah[i1]);
                afh[mi][2] = __float_as_uint(Ah[i0 + 4]);
                afh[mi][3] = __float_as_uint(Ah[i1 + 4]);
                afl[mi][0] = __float_as_uint(Al[i0]);
                afl[mi][1] = __float_as_uint(Al[i1]);
                afl[mi][2] = __float_as_uint(Al[i0 + 4]);
                afl[mi][3] = __float_as_uint(Al[i1 + 4]);
            }
            #pragma unroll
            for (int ni = 0; ni < 4; ni++) {
                int n = wn * 32 + ni * 8 + gid;
                int i0 = (k + tig)     * B_STRIDE + n;
                int i1 = (k + tig + 4) * B_STRIDE + n;
                bfh[ni][0] = __float_as_uint(Bh[i0]);
                bfh[ni][1] = __float_as_uint(Bh[i1]);
                bfl[ni][0] = __float_as_uint(Bl[i0]);
                bfl[ni][1] = __float_as_uint(Bl[i1]);
            }
            #pragma unroll
            for (int mi = 0; mi < 4; mi++)
                #pragma unroll
                for (int ni = 0; ni < 4; ni++) {
                    mma_tf32(acc[mi][ni], afl[mi], bfh[ni]);
                    mma_tf32(acc[mi][ni], afh[mi], bfl[ni]);
                    mma_tf32(acc[mi][ni], afh[mi], bfh[ni]);
                }
        }

        if (more) {
            int nb = cur ^ 1;
            #pragma unroll
            for (int j = 0; j < 4; j++) {
                float4 hi, lo;
                split4(pa[j], hi, lo);
                *(float4*)(sAh[nb] + aoff[j]) = hi;
                *(float4*)(sAl[nb] + aoff[j]) = lo;
                split4(pb[j], hi, lo);
                *(float4*)(sBh[nb] + boff[j]) = hi;
                *(float4*)(sBl[nb] + boff[j]) = lo;
            }
        }
        __syncthreads();
    }

    // ---- epilogue -----------------------------------------------------------
    #pragma unroll
    for (int mi = 0; mi < 4; mi++) {
        int mloc = row0 + wm * 64 + mi * 16 + gid;
        #pragma unroll
        for (int half = 0; half < 2; half++) {
            int m = mloc + half * 8;
            if (m >= M) continue;
            size_t crow = (MODE >= 2) ? (size_t)(rowbase + m) * Nn : (size_t)m * Nn;
            #pragma unroll
            for (int ni = 0; ni < 4; ni++) {
                int n = col0 + wn * 32 + ni * 8 + tig * 2;
                float2 o;
                o.x = acc[mi][ni][half * 2 + 0] + bias[n];
                o.y = acc[mi][ni][half * 2 + 1] + bias[n + 1];
                if (MODE == 1) {
                    int bb = m >> 8;
                    const float* gm = g_mod + bb * DD4 + 2 * DD + n;
                    const float* rx = xres + (size_t)m * DD + n;
                    o.x = rx[0] + gm[0] * o.x;
                    o.y = rx[1] + gm[1] * o.y;
                } else if (MODE == 2) {
                    o.x = gelu_tanh(o.x);
                    o.y = gelu_tanh(o.y);
                }
                *(float2*)(C + crow + n) = o;
            }
        }
    }
}

// ---------------------------------------------------------------------------
// Attention: one block per (head, batch). K,V in smem (stride 73).
// ---------------------------------------------------------------------------
__global__ void attn_kernel() {
    int h = blockIdx.x, b = blockIdx.y;
    extern __shared__ float smn[];
    float* Ks = smn;
    float* Vs = smn + 256 * 73;
    float* Ps = smn + 2 * 256 * 73;

    const float* base = g_qkv + (size_t)b * SEQ * DD3;
    int tid = threadIdx.x;
    for (int i = tid; i < SEQ * HD; i += 256) {
        int r = i / HD, d = i - r * HD;
        size_t g = (size_t)r * DD3 + h * HD + d;
        Ks[r * 73 + d] = base[g + DD];
        Vs[r * 73 + d] = base[g + 2 * DD];
    }
    __syncthreads();

    int warp = tid >> 5, lane = tid & 31;
    float* ps = Ps + warp * 256;
    const float scale = 0.11785113019775793f;

    for (int q = warp; q < SEQ; q += 8) {
        const float* qv = base + (size_t)q * DD3 + h * HD;
        float sloc[8];
        float mx = -1e30f;
        #pragma unroll
        for (int kk = 0; kk < 8; kk++) {
            const float* kv = Ks + (lane + kk * 32) * 73;
            float s = 0.f;
            #pragma unroll
            for (int d = 0; d < HD; d++) s += qv[d] * kv[d];
            s *= scale;
            sloc[kk] = s;
            mx = fmaxf(mx, s);
        }
        #pragma unroll
        for (int o = 16; o; o >>= 1) mx = fmaxf(mx, __shfl_xor_sync(0xffffffffu, mx, o));
        float sum = 0.f;
        #pragma unroll
        for (int kk = 0; kk < 8; kk++) { sloc[kk] = __expf(sloc[kk] - mx); sum += sloc[kk]; }
        #pragma unroll
        for (int o = 16; o; o >>= 1) sum += __shfl_xor_sync(0xffffffffu, sum, o);
        float inv = 1.f / sum;
        #pragma unroll
        for (int kk = 0; kk < 8; kk++) ps[lane + kk * 32] = sloc[kk] * inv;
        __syncwarp();

        float o0 = 0.f, o1 = 0.f, o2 = 0.f;
        for (int k = 0; k < SEQ; k++) {
            float p = ps[k];
            const float* vr = Vs + k * 73;
            o0 += p * vr[lane];
            o1 += p * vr[lane + 32];
            if (lane < 8) o2 += p * vr[lane + 64];
        }
        float* orow = g_ao + (size_t)(b * SEQ + q) * DD + h * HD;
        orow[lane] = o0;
        orow[lane + 32] = o1;
        if (lane < 8) orow[lane + 64] = o2;
    }
}

// ---------------------------------------------------------------------------
// Router: one warp per token.
// ---------------------------------------------------------------------------
__global__ void router_kernel(const float* __restrict__ gw,
                              const float* __restrict__ gb) {
    int t = blockIdx.x * 8 + (threadIdx.x >> 5);
    int lane = threadIdx.x & 31;
    const float* xr = g_nx + (size_t)t * DD;
    float acc[NE];
    #pragma unroll
    for (int e = 0; e < NE; e++) acc[e] = 0.f;
    for (int i = lane; i < DD; i += 32) {
        float v = xr[i];
        const float* g = gw + i * NE;
        #pragma unroll
        for (int e = 0; e < NE; e++) acc[e] += v * g[e];
    }
    #pragma unroll
    for (int e = 0; e < NE; e++)
        #pragma unroll
        for (int o = 16; o; o >>= 1) acc[e] += __shfl_xor_sync(0xffffffffu, acc[e], o);
    if (lane == 0) {
        float best = -1e30f, second = -1e30f; int bi = 0, si = 0;
        #pragma unroll
        for (int e = 0; e < NE; e++) {
            float v = acc[e] + gb[e];
            if (v > best) { second = best; si = bi; best = v; bi = e; }
            else if (v > second) { second = v; si = e; }
        }
        float e1 = __expf(second - best);
        float inv = 1.f / (1.f + e1);
        g_topidx[t * 2] = bi;  g_topidx[t * 2 + 1] = si;
        g_score[t * 2] = inv;  g_score[t * 2 + 1] = e1 * inv;
    }
}

// ---------------------------------------------------------------------------
// Bucketize tokens per expert. Single block.
// ---------------------------------------------------------------------------
__global__ void bucketize_kernel() {
    __shared__ int cnt[NE], off[NE], cur[NE];
    int tid = threadIdx.x;
    if (tid < NE) cnt[tid] = 0;
    __syncthreads();
    for (int t = tid; t < NTOK; t += 256) {
        atomicAdd(&cnt[g_topidx[t * 2]], 1);
        atomicAdd(&cnt[g_topidx[t * 2 + 1]], 1);
    }
    __syncthreads();
    if (tid == 0) {
        int o = 0;
        for (int e = 0; e < NE; e++) {
            off[e] = o; g_off[e] = o; g_cnt[e] = cnt[e];
            o += cnt[e];
        }
    }
    __syncthreads();
    if (tid < NE) cur[tid] = off[tid];
    __syncthreads();
    for (int t = tid; t < NTOK; t += 256) {
        #pragma unroll
        for (int k = 0; k < 2; k++) {
            int e = g_topidx[t * 2 + k];
            int p = atomicAdd(&cur[e], 1);
            g_bucket_tok[p] = t;
            g_slot_of[t * 2 + k] = p;
        }
    }
}

// ---------------------------------------------------------------------------
// Final combine: out += gate_mlp * (s0*eo[slot0] + s1*eo[slot1])
// ---------------------------------------------------------------------------
__global__ void final_kernel(float* __restrict__ out) {
    int t = blockIdx.x;
    int bb = t >> 8;
    int sl0 = g_slot_of[t * 2], sl1 = g_slot_of[t * 2 + 1];
    float s0 = g_score[t * 2], s1 = g_score[t * 2 + 1];
    const float* gm = g_mod + bb * DD4 + 3 * DD;
    const float* e0 = g_eo + (size_t)sl0 * DD;
    const float* e1 = g_eo + (size_t)sl1 * DD;
    float* o = out + (size_t)t * DD;
    for (int i = threadIdx.x; i < DD; i += 256)
        o[i] += gm[i] * (s0 * e0[i] + s1 * e1[i]);
}

// ---------------------------------------------------------------------------
// Launcher
// ---------------------------------------------------------------------------
extern "C" void kernel_launch(void* const* d_in, const int* in_sizes, int n_in,
                              void* d_out, int out_size) {
    (void)in_sizes; (void)n_in; (void)out_size;
    const float* x       = (const float*)d_in[0];
    const float* c       = (const float*)d_in[1];
    const float* qkv_w   = (const float*)d_in[2];
    const float* qkv_b   = (const float*)d_in[3];
    const float* proj_w  = (const float*)d_in[4];
    const float* proj_b  = (const float*)d_in[5];
    const float* adaln_w = (const float*)d_in[6];
    const float* adaln_b = (const float*)d_in[7];
    const float* gate_w  = (const float*)d_in[8];
    const float* gate_b  = (const float*)d_in[9];
    const float* w1      = (const float*)d_in[10];
    const float* b1      = (const float*)d_in[11];
    const float* w2      = (const float*)d_in[12];
    const float* b2      = (const float*)d_in[13];
    float* out = (float*)d_out;

    const int ATTN_SMEM = (2 * 256 * 73 + 8 * 256) * 4;
    cudaFuncSetAttribute(attn_kernel, cudaFuncAttributeMaxDynamicSharedMemorySize, ATTN_SMEM);
    cudaFuncSetAttribute(gemm_tc<0>, cudaFuncAttributeMaxDynamicSharedMemorySize, GEMM_SMEM);
    cudaFuncSetAttribute(gemm_tc<1>, cudaFuncAttributeMaxDynamicSharedMemorySize, GEMM_SMEM);
    cudaFuncSetAttribute(gemm_tc<2>, cudaFuncAttributeMaxDynamicSharedMemorySize, GEMM_SMEM);
    cudaFuncSetAttribute(gemm_tc<3>, cudaFuncAttributeMaxDynamicSharedMemorySize, GEMM_SMEM);

    adaln_kernel<<<dim3(DD4 / 128, BATCH), 128>>>(c, adaln_w, adaln_b);
    ln_kernel<0><<<NTOK, 256>>>(x);
    gemm_tc<0><<<dim3(DD3 / 128, NTOK / 128, 1), 256, GEMM_SMEM>>>(
        qkv_w, qkv_b, nullptr, nullptr, NTOK, DD3, DD);
    attn_kernel<<<dim3(NH, BATCH), 256, ATTN_SMEM>>>();
    gemm_tc<1><<<dim3(DD / 128, NTOK / 128, 1), 256, GEMM_SMEM>>>(
        proj_w, proj_b, x, out, NTOK, DD, DD);
    ln_kernel<1><<<NTOK, 256>>>(out);
    router_kernel<<<NTOK / 8, 256>>>(gate_w, gate_b);
    bucketize_kernel<<<1, 256>>>();
    gemm_tc<2><<<dim3(MH / 128, NTOK * 2 / 128, NE), 256, GEMM_SMEM>>>(
        w1, b1, nullptr, nullptr, 0, MH, DD);
    gemm_tc<3><<<dim3(DD / 128, NTOK * 2 / 128, NE), 256, GEMM_SMEM>>>(
        w2, b2, nullptr, nullptr, 0, DD, MH);
    final_kernel<<<NTOK, 256>>>(out);
}

// round 6
// speedup vs baseline: 1.3898x; 1.3031x over previous
#include <cuda_runtime.h>
#include <cuda_bf16.h>
#include <math.h>
#include <stdint.h>

// ---------------------------------------------------------------------------
#define BATCH 8
#define SEQ   256
#define NTOK  2048
#define DD    1152
#define DD3   3456
#define DD4   4608
#define MH    4608
#define NE    8
#define NH    16
#define HD    72
#define LN_EPS 1e-6f

// ---------------------------------------------------------------------------
// Device scratch (no allocations allowed)
// ---------------------------------------------------------------------------
__device__ __align__(16) float g_mod[BATCH * DD4];
__device__ __align__(16) float g_h[NTOK * DD];
__device__ __align__(16) float g_qkv[NTOK * DD3];
__device__ __align__(16) float g_ao[NTOK * DD];
__device__ __align__(16) float g_nx[NTOK * DD];
__device__ float g_score[NTOK * 2];
__device__ int   g_topidx[NTOK * 2];
__device__ int   g_slot_of[NTOK * 2];
__device__ int   g_bucket_tok[NTOK * 2];
__device__ int   g_off[NE];
__device__ int   g_cnt[NE];
__device__ __align__(16) float g_h1[(size_t)NTOK * 2 * MH];
__device__ __align__(16) float g_eo[(size_t)NTOK * 2 * DD];

// ---------------------------------------------------------------------------
// Helpers
// ---------------------------------------------------------------------------
__device__ __forceinline__ void mma_bf16(float* d, const unsigned* a, const unsigned* b) {
    asm volatile(
        "mma.sync.aligned.m16n8k16.row.col.f32.bf16.bf16.f32 "
        "{%0,%1,%2,%3}, {%4,%5,%6,%7}, {%8,%9}, {%0,%1,%2,%3};"
        : "+f"(d[0]), "+f"(d[1]), "+f"(d[2]), "+f"(d[3])
        : "r"(a[0]), "r"(a[1]), "r"(a[2]), "r"(a[3]), "r"(b[0]), "r"(b[1]));
}
__device__ __forceinline__ float gelu_tanh(float x) {
    float x3 = x * x * x;
    return 0.5f * x * (1.f + tanhf(0.7978845608028654f * (x + 0.044715f * x3)));
}
// split (x0,x1) into packed bf16x2 hi word + lo word (low half = x0)
__device__ __forceinline__ void splitpack2(float x0, float x1, unsigned& h, unsigned& l) {
    __nv_bfloat16 h0 = __float2bfloat16_rn(x0);
    __nv_bfloat16 h1 = __float2bfloat16_rn(x1);
    float r0 = x0 - __bfloat162float(h0);
    float r1 = x1 - __bfloat162float(h1);
    __nv_bfloat16 l0 = __float2bfloat16_rn(r0);
    __nv_bfloat16 l1 = __float2bfloat16_rn(r1);
    h = ((unsigned)__bfloat16_as_ushort(h1) << 16) | __bfloat16_as_ushort(h0);
    l = ((unsigned)__bfloat16_as_ushort(l1) << 16) | __bfloat16_as_ushort(l0);
}

// ---------------------------------------------------------------------------
// adaLN modulation: mod = silu(c) @ adaln_w + adaln_b
// ---------------------------------------------------------------------------
__global__ void adaln_kernel(const float* __restrict__ c,
                             const float* __restrict__ w,
                             const float* __restrict__ b) {
    int bb = blockIdx.y;
    int col = blockIdx.x * 128 + threadIdx.x;
    __shared__ float cs[DD];
    for (int i = threadIdx.x; i < DD; i += 128) {
        float v = c[bb * DD + i];
        cs[i] = v / (1.f + __expf(-v));
    }
    __syncthreads();
    float acc = b[col];
    #pragma unroll 4
    for (int i = 0; i < DD; i++)
        acc += cs[i] * w[(size_t)i * DD4 + col];
    g_mod[bb * DD4 + col] = acc;
}

// ---------------------------------------------------------------------------
// LayerNorm. MODE 0: h = ln(x)*(1+scale)+shift -> g_h ; MODE 1: -> g_nx
// ---------------------------------------------------------------------------
template <int MODE>
__global__ void ln_kernel(const float* __restrict__ in) {
    int t = blockIdx.x;
    const float* xr = in + (size_t)t * DD;
    int tid = threadIdx.x, lane = tid & 31, warp = tid >> 5;
    float s = 0.f, s2 = 0.f;
    for (int i = tid; i < DD; i += 256) { float v = xr[i]; s += v; s2 += v * v; }
    #pragma unroll
    for (int o = 16; o; o >>= 1) {
        s  += __shfl_xor_sync(0xffffffffu, s,  o);
        s2 += __shfl_xor_sync(0xffffffffu, s2, o);
    }
    __shared__ float ws[8], ws2[8], mean_s, rstd_s;
    if (lane == 0) { ws[warp] = s; ws2[warp] = s2; }
    __syncthreads();
    if (warp == 0) {
        s  = (lane < 8) ? ws[lane]  : 0.f;
        s2 = (lane < 8) ? ws2[lane] : 0.f;
        #pragma unroll
        for (int o = 4; o; o >>= 1) {
            s  += __shfl_xor_sync(0xffffffffu, s,  o);
            s2 += __shfl_xor_sync(0xffffffffu, s2, o);
        }
        if (lane == 0) {
            float m = s * (1.f / DD);
            float v = s2 * (1.f / DD) - m * m;
            mean_s = m; rstd_s = rsqrtf(v + LN_EPS);
        }
    }
    __syncthreads();
    float m = mean_s, rstd = rstd_s;
    int bb = t >> 8;
    for (int i = tid; i < DD; i += 256) {
        float v = (xr[i] - m) * rstd;
        if (MODE == 0) {
            float sc = g_mod[bb * DD4 + DD + i];
            float sh = g_mod[bb * DD4 + i];
            g_h[(size_t)t * DD + i] = v * (1.f + sc) + sh;
        } else {
            g_nx[(size_t)t * DD + i] = v;
        }
    }
}

// ---------------------------------------------------------------------------
// bf16x3 tensor-core GEMM via mma.sync m16n8k16 (compiles for compute_103).
// acc = Ahi*Bhi + Alo*Bhi + Ahi*Blo  (fp32 accumulate; ~3e-5 rel err)
// CTA tile 128x128, 8 warps (2x4), warp tile 64x32, K-chunk 32,
// double-buffered smem + register prefetch. bf16 pairs packed along K.
//   MODE 0: g_qkv = g_h @ qkv_w + b
//   MODE 1: d_out = xres + gate_msa * (g_ao @ proj_w + b)
//   MODE 2: g_h1 = gelu(gather(g_nx) @ w1[e] + b1[e])
//   MODE 3: g_eo = g_h1 @ w2[e] + b2[e]
// W is the ORIGINAL [K][N] row-major weight (row.col mma reads B[k][n]).
// ---------------------------------------------------------------------------
#define A_STRIDE 20          // uint32 words per A row: 16 data + 4 pad
#define B_STRIDE 136         // uint32 words per B k2-row: 128 data + 8 pad
#define A_WORDS (128 * A_STRIDE)                 // 2560
#define B_WORDS (16 * B_STRIDE)                  // 2176
#define BUF_WORDS (2 * A_WORDS + 2 * B_WORDS)    // 9472 (hi+lo)
#define GEMM_SMEM (2 * BUF_WORDS * 4)            // 75776 B

template <int MODE>
__global__ __launch_bounds__(256, 1)
void gemm_tc(const float* __restrict__ W, const float* __restrict__ bias,
             const float* __restrict__ xres, float* __restrict__ Cout,
             int M, int Nn, int Kk) {
    int e = blockIdx.z;
    const float* A;
    float* C;
    const int* gather = nullptr;
    int rowbase = 0;

    if (MODE == 0)      { A = g_h;  C = g_qkv; }
    else if (MODE == 1) { A = g_ao; C = Cout; }
    else if (MODE == 2) {
        M = g_cnt[e]; rowbase = g_off[e];
        gather = g_bucket_tok + rowbase;
        A = g_nx;
        W = W + (size_t)e * DD * MH;
        bias = bias + e * MH;
        C = g_h1;
    } else {
        M = g_cnt[e]; rowbase = g_off[e];
        A = g_h1 + (size_t)rowbase * MH;
        W = W + (size_t)e * MH * DD;
        bias = bias + e * DD;
        C = g_eo;
    }

    int row0 = blockIdx.y * 128;
    if (row0 >= M) return;
    int col0 = blockIdx.x * 128;

    extern __shared__ __align__(16) unsigned smu[];
    unsigned* sAh[2] = { smu,                           smu + BUF_WORDS };
    unsigned* sAl[2] = { smu + A_WORDS,                 smu + BUF_WORDS + A_WORDS };
    unsigned* sBh[2] = { smu + 2 * A_WORDS,             smu + BUF_WORDS + 2 * A_WORDS };
    unsigned* sBl[2] = { smu + 2 * A_WORDS + B_WORDS,   smu + BUF_WORDS + 2 * A_WORDS + B_WORDS };

    int tid = threadIdx.x;
    int lane = tid & 31, wid = tid >> 5;
    int gid = lane >> 2, tig = lane & 3;
    int wm = wid >> 2, wn = wid & 3;       // warp tile: rows wm*64, cols wn*32

    // ---- staging maps -----------------------------------------------------
    // A: thread handles rows (tid>>3)+32j (j<4), k-float4 fA = tid&7
    int fA = tid & 7;
    const float* arow[4];
    unsigned aoff[4];
    #pragma unroll
    for (int j = 0; j < 4; j++) {
        int r = (tid >> 3) + 32 * j;
        int gr = row0 + r;
        if (gr > M - 1) gr = M - 1;
        if (MODE == 2) arow[j] = A + (size_t)gather[gr] * Kk + fA * 4;
        else           arow[j] = A + (size_t)gr * Kk + fA * 4;
        aoff[j] = (unsigned)(r * A_STRIDE + fA * 2);
    }
    // B: thread handles k2-rows (tid>>5)+8j (j<2), n-float4 fB = tid&31
    int fB = tid & 31;
    const float* brow0[2];
    const float* brow1[2];
    unsigned boff[2];
    #pragma unroll
    for (int j = 0; j < 2; j++) {
        int k2r = (tid >> 5) + 8 * j;
        brow0[j] = W + (size_t)(2 * k2r)     * Nn + col0 + fB * 4;
        brow1[j] = W + (size_t)(2 * k2r + 1) * Nn + col0 + fB * 4;
        boff[j] = (unsigned)(k2r * B_STRIDE + fB * 4);
    }
    size_t bstep = (size_t)32 * Nn;

    float acc[4][4][4];
    #pragma unroll
    for (int mi = 0; mi < 4; mi++)
        #pragma unroll
        for (int ni = 0; ni < 4; ni++)
            #pragma unroll
            for (int r = 0; r < 4; r++) acc[mi][ni][r] = 0.f;

    // stage one chunk into buffer buf from registers
    auto stage = [&](int buf, const float4* pa, const float4* pb0, const float4* pb1) {
        #pragma unroll
        for (int j = 0; j < 4; j++) {
            unsigned h0, l0, h1, l1;
            splitpack2(pa[j].x, pa[j].y, h0, l0);
            splitpack2(pa[j].z, pa[j].w, h1, l1);
            *(uint2*)(sAh[buf] + aoff[j]) = make_uint2(h0, h1);
            *(uint2*)(sAl[buf] + aoff[j]) = make_uint2(l0, l1);
        }
        #pragma unroll
        for (int j = 0; j < 2; j++) {
            unsigned h[4], l[4];
            splitpack2(pb0[j].x, pb1[j].x, h[0], l[0]);
            splitpack2(pb0[j].y, pb1[j].y, h[1], l[1]);
            splitpack2(pb0[j].z, pb1[j].z, h[2], l[2]);
            splitpack2(pb0[j].w, pb1[j].w, h[3], l[3]);
            *(uint4*)(sBh[buf] + boff[j]) = make_uint4(h[0], h[1], h[2], h[3]);
            *(uint4*)(sBl[buf] + boff[j]) = make_uint4(l[0], l[1], l[2], l[3]);
        }
    };

    // ---- prologue: stage chunk 0 into buffer 0 -----------------------------
    {
        float4 pa[4], pb0[2], pb1[2];
        #pragma unroll
        for (int j = 0; j < 4; j++) pa[j] = *(const float4*)(arow[j]);
        #pragma unroll
        for (int j = 0; j < 2; j++) {
            pb0[j] = *(const float4*)(brow0[j]);
            pb1[j] = *(const float4*)(brow1[j]);
        }
        stage(0, pa, pb0, pb1);
    }
    __syncthreads();

    int nch = Kk / 32;
    for (int c = 0; c < nch; c++) {
        int cur = c & 1;
        float4 pa[4], pb0[2], pb1[2];
        bool more = (c + 1 < nch);
        if (more) {
            int k0n = (c + 1) * 32;
            size_t bo = (size_t)(c + 1) * bstep;
            #pragma unroll
            for (int j = 0; j < 4; j++) pa[j] = *(const float4*)(arow[j] + k0n);
            #pragma unroll
            for (int j = 0; j < 2; j++) {
                pb0[j] = *(const float4*)(brow0[j] + bo);
                pb1[j] = *(const float4*)(brow1[j] + bo);
            }
        }

        const unsigned* Ah = sAh[cur];
        const unsigned* Al = sAl[cur];
        const unsigned* Bh = sBh[cur];
        const unsigned* Bl = sBl[cur];
        #pragma unroll
        for (int ks = 0; ks < 2; ks++) {
            int kb = ks * 8;
            unsigned afh[4][4], afl[4][4];
            unsigned bfh[4][2], bfl[4][2];
            #pragma unroll
            for (int mi = 0; mi < 4; mi++) {
                int m = wm * 64 + mi * 16 + gid;
                int i0 = m * A_STRIDE + kb + tig;
                int i1 = (m + 8) * A_STRIDE + kb + tig;
                afh[mi][0] = Ah[i0];     afh[mi][1] = Ah[i1];
                afh[mi][2] = Ah[i0 + 4]; afh[mi][3] = Ah[i1 + 4];
                afl[mi][0] = Al[i0];     afl[mi][1] = Al[i1];
                afl[mi][2] = Al[i0 + 4]; afl[mi][3] = Al[i1 + 4];
            }
            #pragma unroll
            for (int ni = 0; ni < 4; ni++) {
                int n = wn * 32 + ni * 8 + gid;
                int j0 = (kb + tig) * B_STRIDE + n;
                int j1 = (kb + tig + 4) * B_STRIDE + n;
                bfh[ni][0] = Bh[j0]; bfh[ni][1] = Bh[j1];
                bfl[ni][0] = Bl[j0]; bfl[ni][1] = Bl[j1];
            }
            #pragma unroll
            for (int mi = 0; mi < 4; mi++)
                #pragma unroll
                for (int ni = 0; ni < 4; ni++) {
                    mma_bf16(acc[mi][ni], afl[mi], bfh[ni]);
                    mma_bf16(acc[mi][ni], afh[mi], bfl[ni]);
                    mma_bf16(acc[mi][ni], afh[mi], bfh[ni]);
                }
        }

        if (more) {
            stage(cur ^ 1, pa, pb0, pb1);
        }
        __syncthreads();
    }

    // ---- epilogue -----------------------------------------------------------
    #pragma unroll
    for (int mi = 0; mi < 4; mi++) {
        int mloc = row0 + wm * 64 + mi * 16 + gid;
        #pragma unroll
        for (int half = 0; half < 2; half++) {
            int m = mloc + half * 8;
            if (m >= M) continue;
            size_t crow = (MODE >= 2) ? (size_t)(rowbase + m) * Nn : (size_t)m * Nn;
            #pragma unroll
            for (int ni = 0; ni < 4; ni++) {
                int n = col0 + wn * 32 + ni * 8 + tig * 2;
                float2 o;
                o.x = acc[mi][ni][half * 2 + 0] + bias[n];
                o.y = acc[mi][ni][half * 2 + 1] + bias[n + 1];
                if (MODE == 1) {
                    int bb = m >> 8;
                    const float* gm = g_mod + bb * DD4 + 2 * DD + n;
                    const float* rx = xres + (size_t)m * DD + n;
                    o.x = rx[0] + gm[0] * o.x;
                    o.y = rx[1] + gm[1] * o.y;
                } else if (MODE == 2) {
                    o.x = gelu_tanh(o.x);
                    o.y = gelu_tanh(o.y);
                }
                *(float2*)(C + crow + n) = o;
            }
        }
    }
}

// ---------------------------------------------------------------------------
// Attention: one block per (head, batch, half). K,V in smem (stride 73).
// ---------------------------------------------------------------------------
__global__ void attn_kernel() {
    int h = blockIdx.x, b = blockIdx.y, z = blockIdx.z;
    extern __shared__ float smn[];
    float* Ks = smn;
    float* Vs = smn + 256 * 73;
    float* Ps = smn + 2 * 256 * 73;

    const float* base = g_qkv + (size_t)b * SEQ * DD3;
    int tid = threadIdx.x;
    for (int i = tid; i < SEQ * HD; i += 256) {
        int r = i / HD, d = i - r * HD;
        size_t g = (size_t)r * DD3 + h * HD + d;
        Ks[r * 73 + d] = base[g + DD];
        Vs[r * 73 + d] = base[g + 2 * DD];
    }
    __syncthreads();

    int warp = tid >> 5, lane = tid & 31;
    float* ps = Ps + warp * 256;
    const float scale = 0.11785113019775793f;

    int qbase = z * 128;
    for (int q = qbase + warp; q < qbase + 128; q += 8) {
        const float* qv = base + (size_t)q * DD3 + h * HD;
        float sloc[8];
        float mx = -1e30f;
        #pragma unroll
        for (int kk = 0; kk < 8; kk++) {
            const float* kv = Ks + (lane + kk * 32) * 73;
            float s = 0.f;
            #pragma unroll
            for (int d = 0; d < HD; d++) s += qv[d] * kv[d];
            s *= scale;
            sloc[kk] = s;
            mx = fmaxf(mx, s);
        }
        #pragma unroll
        for (int o = 16; o; o >>= 1) mx = fmaxf(mx, __shfl_xor_sync(0xffffffffu, mx, o));
        float sum = 0.f;
        #pragma unroll
        for (int kk = 0; kk < 8; kk++) { sloc[kk] = __expf(sloc[kk] - mx); sum += sloc[kk]; }
        #pragma unroll
        for (int o = 16; o; o >>= 1) sum += __shfl_xor_sync(0xffffffffu, sum, o);
        float inv = 1.f / sum;
        #pragma unroll
        for (int kk = 0; kk < 8; kk++) ps[lane + kk * 32] = sloc[kk] * inv;
        __syncwarp();

        float o0 = 0.f, o1 = 0.f, o2 = 0.f;
        for (int k = 0; k < SEQ; k++) {
            float p = ps[k];
            const float* vr = Vs + k * 73;
            o0 += p * vr[lane];
            o1 += p * vr[lane + 32];
            if (lane < 8) o2 += p * vr[lane + 64];
        }
        float* orow = g_ao + (size_t)(b * SEQ + q) * DD + h * HD;
        orow[lane] = o0;
        orow[lane + 32] = o1;
        if (lane < 8) orow[lane + 64] = o2;
    }
}

// ---------------------------------------------------------------------------
// Router: one warp per token.
// ---------------------------------------------------------------------------
__global__ void router_kernel(const float* __restrict__ gw,
                              const float* __restrict__ gb) {
    int t = blockIdx.x * 8 + (threadIdx.x >> 5);
    int lane = threadIdx.x & 31;
    const float* xr = g_nx + (size_t)t * DD;
    float acc[NE];
    #pragma unroll
    for (int e = 0; e < NE; e++) acc[e] = 0.f;
    for (int i = lane; i < DD; i += 32) {
        float v = xr[i];
        const float* g = gw + i * NE;
        #pragma unroll
        for (int e = 0; e < NE; e++) acc[e] += v * g[e];
    }
    #pragma unroll
    for (int e = 0; e < NE; e++)
        #pragma unroll
        for (int o = 16; o; o >>= 1) acc[e] += __shfl_xor_sync(0xffffffffu, acc[e], o);
    if (lane == 0) {
        float best = -1e30f, second = -1e30f; int bi = 0, si = 0;
        #pragma unroll
        for (int e = 0; e < NE; e++) {
            float v = acc[e] + gb[e];
            if (v > best) { second = best; si = bi; best = v; bi = e; }
            else if (v > second) { second = v; si = e; }
        }
        float e1 = __expf(second - best);
        float inv = 1.f / (1.f + e1);
        g_topidx[t * 2] = bi;  g_topidx[t * 2 + 1] = si;
        g_score[t * 2] = inv;  g_score[t * 2 + 1] = e1 * inv;
    }
}

// ---------------------------------------------------------------------------
// Bucketize tokens per expert. Single block.
// ---------------------------------------------------------------------------
__global__ void bucketize_kernel() {
    __shared__ int cnt[NE], off[NE], cur[NE];
    int tid = threadIdx.x;
    if (tid < NE) cnt[tid] = 0;
    __syncthreads();
    for (int t = tid; t < NTOK; t += 256) {
        atomicAdd(&cnt[g_topidx[t * 2]], 1);
        atomicAdd(&cnt[g_topidx[t * 2 + 1]], 1);
    }
    __syncthreads();
    if (tid == 0) {
        int o = 0;
        for (int e = 0; e < NE; e++) {
            off[e] = o; g_off[e] = o; g_cnt[e] = cnt[e];
            o += cnt[e];
        }
    }
    __syncthreads();
    if (tid < NE) cur[tid] = off[tid];
    __syncthreads();
    for (int t = tid; t < NTOK; t += 256) {
        #pragma unroll
        for (int k = 0; k < 2; k++) {
            int e = g_topidx[t * 2 + k];
            int p = atomicAdd(&cur[e], 1);
            g_bucket_tok[p] = t;
            g_slot_of[t * 2 + k] = p;
        }
    }
}

// ---------------------------------------------------------------------------
// Final combine: out += gate_mlp * (s0*eo[slot0] + s1*eo[slot1])
// ---------------------------------------------------------------------------
__global__ void final_kernel(float* __restrict__ out) {
    int t = blockIdx.x;
    int bb = t >> 8;
    int sl0 = g_slot_of[t * 2], sl1 = g_slot_of[t * 2 + 1];
    float s0 = g_score[t * 2], s1 = g_score[t * 2 + 1];
    const float* gm = g_mod + bb * DD4 + 3 * DD;
    const float* e0 = g_eo + (size_t)sl0 * DD;
    const float* e1 = g_eo + (size_t)sl1 * DD;
    float* o = out + (size_t)t * DD;
    for (int i = threadIdx.x; i < DD; i += 256)
        o[i] += gm[i] * (s0 * e0[i] + s1 * e1[i]);
}

// ---------------------------------------------------------------------------
// Launcher
// ---------------------------------------------------------------------------
extern "C" void kernel_launch(void* const* d_in, const int* in_sizes, int n_in,
                              void* d_out, int out_size) {
    (void)in_sizes; (void)n_in; (void)out_size;
    const float* x       = (const float*)d_in[0];
    const float* c       = (const float*)d_in[1];
    const float* qkv_w   = (const float*)d_in[2];
    const float* qkv_b   = (const float*)d_in[3];
    const float* proj_w  = (const float*)d_in[4];
    const float* proj_b  = (const float*)d_in[5];
    const float* adaln_w = (const float*)d_in[6];
    const float* adaln_b = (const float*)d_in[7];
    const float* gate_w  = (const float*)d_in[8];
    const float* gate_b  = (const float*)d_in[9];
    const float* w1      = (const float*)d_in[10];
    const float* b1      = (const float*)d_in[11];
    const float* w2      = (const float*)d_in[12];
    const float* b2      = (const float*)d_in[13];
    float* out = (float*)d_out;

    const int ATTN_SMEM = (2 * 256 * 73 + 8 * 256) * 4;
    cudaFuncSetAttribute(attn_kernel, cudaFuncAttributeMaxDynamicSharedMemorySize, ATTN_SMEM);
    cudaFuncSetAttribute(gemm_tc<0>, cudaFuncAttributeMaxDynamicSharedMemorySize, GEMM_SMEM);
    cudaFuncSetAttribute(gemm_tc<1>, cudaFuncAttributeMaxDynamicSharedMemorySize, GEMM_SMEM);
    cudaFuncSetAttribute(gemm_tc<2>, cudaFuncAttributeMaxDynamicSharedMemorySize, GEMM_SMEM);
    cudaFuncSetAttribute(gemm_tc<3>, cudaFuncAttributeMaxDynamicSharedMemorySize, GEMM_SMEM);

    adaln_kernel<<<dim3(DD4 / 128, BATCH), 128>>>(c, adaln_w, adaln_b);
    ln_kernel<0><<<NTOK, 256>>>(x);
    gemm_tc<0><<<dim3(DD3 / 128, NTOK / 128, 1), 256, GEMM_SMEM>>>(
        qkv_w, qkv_b, nullptr, nullptr, NTOK, DD3, DD);
    attn_kernel<<<dim3(NH, BATCH, 2), 256, ATTN_SMEM>>>();
    gemm_tc<1><<<dim3(DD / 128, NTOK / 128, 1), 256, GEMM_SMEM>>>(
        proj_w, proj_b, x, out, NTOK, DD, DD);
    ln_kernel<1><<<NTOK, 256>>>(out);
    router_kernel<<<NTOK / 8, 256>>>(gate_w, gate_b);
    bucketize_kernel<<<1, 256>>>();
    gemm_tc<2><<<dim3(MH / 128, NTOK * 2 / 128, NE), 256, GEMM_SMEM>>>(
        w1, b1, nullptr, nullptr, 0, MH, DD);
    gemm_tc<3><<<dim3(DD / 128, NTOK * 2 / 128, NE), 256, GEMM_SMEM>>>(
        w2, b2, nullptr, nullptr, 0, DD, MH);
    final_kernel<<<NTOK, 256>>>(out);
}